// round 1
// baseline (speedup 1.0000x reference)
#include <cuda_runtime.h>
#include <cstdint>

// Problem constants (match reference)
#define PN 8
#define PK 8
#define PH 512
#define PW 512
#define PC 4
#define PP 100000
#define HW (PH * PW)

// One thread per pixel (n, h, w). K=8 front-to-back composite, C=4 channels.
// pix_idxs: [N,K,H,W] int32, alphas: [N,K,H,W] f32, ptclds: [C,P] f32
// out images: [N,C,H,W] f32; optional mask appended: [N,H,W] f32 (1.0 = foreground)
__global__ __launch_bounds__(256) void alpha_composite_kernel(
    const int* __restrict__ pix_idxs,
    const float* __restrict__ alphas,
    const float* __restrict__ ptclds,
    float* __restrict__ out,
    int write_mask)
{
    int t = blockIdx.x * blockDim.x + threadIdx.x;
    const int total = PN * HW;
    if (t >= total) return;

    int n = t / HW;
    int hw = t - n * HW;

    const int base = n * (PK * HW) + hw;  // element offset of (n, k=0, h, w)

    // Background test: entire list is -1 iff first entry is -1
    int idx0 = __ldg(&pix_idxs[base]);

    float acc0 = 0.f, acc1 = 0.f, acc2 = 0.f, acc3 = 0.f;
    float T = 1.0f;

    if (idx0 >= 0) {
        #pragma unroll
        for (int k = 0; k < PK; ++k) {
            int idx = __ldg(&pix_idxs[base + k * HW]);
            if (idx < 0) break;  // trailing padding
            float a = __ldg(&alphas[base + k * HW]);
            float w = a * T;
            T *= (1.0f - a);
            acc0 = fmaf(w, __ldg(&ptclds[0 * PP + idx]), acc0);
            acc1 = fmaf(w, __ldg(&ptclds[1 * PP + idx]), acc1);
            acc2 = fmaf(w, __ldg(&ptclds[2 * PP + idx]), acc2);
            acc3 = fmaf(w, __ldg(&ptclds[3 * PP + idx]), acc3);
        }
    } else {
        // background color (0,0,0,1)
        acc0 = 0.f; acc1 = 0.f; acc2 = 0.f; acc3 = 1.f;
    }

    // out images: [N, C, H, W]
    float* o = out + n * (PC * HW) + hw;
    o[0 * HW] = acc0;
    o[1 * HW] = acc1;
    o[2 * HW] = acc2;
    o[3 * HW] = acc3;

    if (write_mask) {
        // mask = ~bg_mask, appended after images as float 1.0/0.0
        out[(int64_t)PN * PC * HW + t] = (idx0 >= 0) ? 1.0f : 0.0f;
    }
}

extern "C" void kernel_launch(void* const* d_in, const int* in_sizes, int n_in,
                              void* d_out, int out_size) {
    const int* pix_idxs = (const int*)d_in[0];
    const float* alphas = (const float*)d_in[1];
    const float* ptclds = (const float*)d_in[2];
    float* out = (float*)d_out;

    const int img_elems = PN * PC * HW;          // 8*4*512*512
    const int mask_elems = PN * HW;              // 8*512*512
    int write_mask = (out_size >= img_elems + mask_elems) ? 1 : 0;

    const int total = PN * HW;
    const int threads = 256;
    const int blocks = (total + threads - 1) / threads;
    alpha_composite_kernel<<<blocks, threads>>>(pix_idxs, alphas, ptclds, out, write_mask);
}

// round 2
// speedup vs baseline: 3.0384x; 3.0384x over previous
#include <cuda_runtime.h>
#include <cstdint>

// Problem constants (match reference)
#define PN 8
#define PK 8
#define PH 512
#define PW 512
#define PC 4
#define PP 100000
#define HW (PH * PW)

// AoS copy of the point cloud: one float4 per point (all 4 channels),
// so each gather is a single 16B load hitting one 32B L2 sector.
__device__ float4 g_pts[PP];

__global__ __launch_bounds__(256) void transpose_ptclds_kernel(
    const float* __restrict__ ptclds)
{
    int p = blockIdx.x * blockDim.x + threadIdx.x;
    if (p >= PP) return;
    float4 v;
    v.x = ptclds[0 * PP + p];
    v.y = ptclds[1 * PP + p];
    v.z = ptclds[2 * PP + p];
    v.w = ptclds[3 * PP + p];
    g_pts[p] = v;
}

// One thread per pixel (n, h, w). K=8 front-to-back composite, C=4 channels.
__global__ __launch_bounds__(256) void alpha_composite_kernel(
    const int* __restrict__ pix_idxs,
    const float* __restrict__ alphas,
    float* __restrict__ out,
    int write_mask)
{
    int t = blockIdx.x * blockDim.x + threadIdx.x;
    const int total = PN * HW;
    if (t >= total) return;

    int n = t / HW;
    int hw = t - n * HW;

    const int base = n * (PK * HW) + hw;  // element offset of (n, k=0, h, w)

    int idx0 = __ldg(&pix_idxs[base]);

    float acc0 = 0.f, acc1 = 0.f, acc2 = 0.f, acc3 = 0.f;
    float T = 1.0f;

    if (idx0 >= 0) {
        #pragma unroll
        for (int k = 0; k < PK; ++k) {
            int idx = __ldg(&pix_idxs[base + k * HW]);
            if (idx < 0) break;  // trailing padding
            float a = __ldg(&alphas[base + k * HW]);
            float w = a * T;
            T *= (1.0f - a);
            float4 f = __ldg(&g_pts[idx]);
            acc0 = fmaf(w, f.x, acc0);
            acc1 = fmaf(w, f.y, acc1);
            acc2 = fmaf(w, f.z, acc2);
            acc3 = fmaf(w, f.w, acc3);
        }
    } else {
        // background color (0,0,0,1)
        acc3 = 1.f;
    }

    // out images: [N, C, H, W]
    float* o = out + n * (PC * HW) + hw;
    o[0 * HW] = acc0;
    o[1 * HW] = acc1;
    o[2 * HW] = acc2;
    o[3 * HW] = acc3;

    if (write_mask) {
        // mask = ~bg_mask, appended after images as float 1.0/0.0
        out[(int64_t)PN * PC * HW + t] = (idx0 >= 0) ? 1.0f : 0.0f;
    }
}

extern "C" void kernel_launch(void* const* d_in, const int* in_sizes, int n_in,
                              void* d_out, int out_size) {
    const int* pix_idxs = (const int*)d_in[0];
    const float* alphas = (const float*)d_in[1];
    const float* ptclds = (const float*)d_in[2];
    float* out = (float*)d_out;

    const int img_elems = PN * PC * HW;          // 8*4*512*512
    const int mask_elems = PN * HW;              // 8*512*512
    int write_mask = (out_size >= img_elems + mask_elems) ? 1 : 0;

    transpose_ptclds_kernel<<<(PP + 255) / 256, 256>>>(ptclds);

    const int total = PN * HW;
    const int threads = 256;
    const int blocks = (total + threads - 1) / threads;
    alpha_composite_kernel<<<blocks, threads>>>(pix_idxs, alphas, out, write_mask);
}

// round 5
// speedup vs baseline: 3.1133x; 1.0247x over previous
#include <cuda_runtime.h>
#include <cstdint>

// Problem constants (match reference)
#define PN 8
#define PK 8
#define PH 512
#define PW 512
#define PC 4
#define PP 100000
#define HW (PH * PW)

// AoS copy of the point cloud: one float4 per point (all 4 channels),
// so each gather is a single 16B load hitting one 32B L2 sector.
__device__ float4 g_pts[PP];

__global__ __launch_bounds__(256) void transpose_ptclds_kernel(
    const float* __restrict__ ptclds)
{
    int p = blockIdx.x * blockDim.x + threadIdx.x;
    if (p >= PP) return;
    float4 v;
    v.x = ptclds[0 * PP + p];
    v.y = ptclds[1 * PP + p];
    v.z = ptclds[2 * PP + p];
    v.w = ptclds[3 * PP + p];
    g_pts[p] = v;
}

// One thread per PAIR of adjacent pixels along W. Break-free masked loop:
// invalid entries get weight 0 and index clamped to 0, so the gather is safe
// and the accumulation exact. 16 independent gathers per thread maximize MLP.
__global__ __launch_bounds__(256) void alpha_composite_kernel(
    const int* __restrict__ pix_idxs,
    const float* __restrict__ alphas,
    float* __restrict__ out,
    int write_mask)
{
    int t = blockIdx.x * blockDim.x + threadIdx.x;
    const int totalPairs = PN * HW / 2;
    if (t >= totalPairs) return;

    int pi = t * 2;                 // first pixel of the pair
    int n = pi / HW;
    int hw = pi - n * HW;           // even

    const int base = n * (PK * HW) + hw;  // element offset of (n, k=0, h, w)

    int2 v0 = __ldg((const int2*)&pix_idxs[base]);
    bool bgA = v0.x < 0;
    bool bgB = v0.y < 0;

    float a0A = 0.f, a1A = 0.f, a2A = 0.f, a3A = 0.f, TA = 1.f;
    float a0B = 0.f, a1B = 0.f, a2B = 0.f, a3B = 0.f, TB = 1.f;

    if (!(bgA && bgB)) {
        #pragma unroll
        for (int k = 0; k < PK; ++k) {
            int2 v = (k == 0) ? v0 : __ldg((const int2*)&pix_idxs[base + k * HW]);
            float2 al = __ldg((const float2*)&alphas[base + k * HW]);

            float aA = (v.x >= 0) ? al.x : 0.f;
            float aB = (v.y >= 0) ? al.y : 0.f;
            int iA = (v.x >= 0) ? v.x : 0;
            int iB = (v.y >= 0) ? v.y : 0;

            float wA = aA * TA;  TA -= wA;    // TA *= (1 - aA)
            float wB = aB * TB;  TB -= wB;

            float4 fA = __ldg(&g_pts[iA]);
            float4 fB = __ldg(&g_pts[iB]);

            a0A = fmaf(wA, fA.x, a0A);
            a1A = fmaf(wA, fA.y, a1A);
            a2A = fmaf(wA, fA.z, a2A);
            a3A = fmaf(wA, fA.w, a3A);
            a0B = fmaf(wB, fB.x, a0B);
            a1B = fmaf(wB, fB.y, a1B);
            a2B = fmaf(wB, fB.z, a2B);
            a3B = fmaf(wB, fB.w, a3B);
        }
    }

    if (bgA) { a0A = 0.f; a1A = 0.f; a2A = 0.f; a3A = 1.f; }
    if (bgB) { a0B = 0.f; a1B = 0.f; a2B = 0.f; a3B = 1.f; }

    // out images: [N, C, H, W]; hw even so float2 stores are 8B aligned
    float* o = out + n * (PC * HW) + hw;
    *(float2*)&o[0 * HW] = make_float2(a0A, a0B);
    *(float2*)&o[1 * HW] = make_float2(a1A, a1B);
    *(float2*)&o[2 * HW] = make_float2(a2A, a2B);
    *(float2*)&o[3 * HW] = make_float2(a3A, a3B);

    if (write_mask) {
        // mask = ~bg_mask, appended after images as float 1.0/0.0
        *(float2*)&out[(int64_t)PN * PC * HW + pi] =
            make_float2(bgA ? 0.f : 1.f, bgB ? 0.f : 1.f);
    }
}

extern "C" void kernel_launch(void* const* d_in, const int* in_sizes, int n_in,
                              void* d_out, int out_size) {
    const int* pix_idxs = (const int*)d_in[0];
    const float* alphas = (const float*)d_in[1];
    const float* ptclds = (const float*)d_in[2];
    float* out = (float*)d_out;

    const int img_elems = PN * PC * HW;          // 8*4*512*512
    const int mask_elems = PN * HW;              // 8*512*512
    int write_mask = (out_size >= img_elems + mask_elems) ? 1 : 0;

    transpose_ptclds_kernel<<<(PP + 255) / 256, 256>>>(ptclds);

    const int totalPairs = PN * HW / 2;
    const int threads = 256;
    const int blocks = (totalPairs + threads - 1) / threads;
    alpha_composite_kernel<<<blocks, threads>>>(pix_idxs, alphas, out, write_mask);
}